// round 5
// baseline (speedup 1.0000x reference)
#include <cuda_runtime.h>
#include <cuda_fp16.h>
#include <cstdint>

// ---------------- problem dims (fixed) ----------------
#define QB 32
#define QT 1024
#define QD 1152
#define QH 4608
#define QM (QB*QT)          // 32768 tokens

// ---------------- scratch (__device__ globals) ------
__device__ __half  g_q1 [(size_t)QM*QD];      // quantized input, exact ints (fp16)
__device__ int8_t  g_q1b[(size_t)QM*QD];      // same, int8 (for IMMA lo path)
__device__ float   g_scale1[QM];
__device__ __half  g_w1hi[(size_t)QH*QD];     // fp16(W1)
__device__ int8_t  g_w1r [(size_t)QH*QD];     // int8 residual quant of W1-fp16(W1)
__device__ float   g_w1rs[QH];                // per-output-column residual scale
__device__ __half  g_w2h [(size_t)QD*QH];
__device__ float   g_h   [(size_t)QM*QH];     // fc1 output (fp32, post-GELU)
__device__ float   g_scale2[QM];
__device__ __half  g_q2 [(size_t)QM*QH];

// ---------------- low-level helpers ----------------
__device__ __forceinline__ uint32_t smem_u32(const void* p){
    uint32_t a;
    asm("{ .reg .u64 t; cvta.to.shared.u64 t, %1; cvt.u32.u64 %0, t; }" : "=r"(a) : "l"(p));
    return a;
}
__device__ __forceinline__ void cp16(uint32_t saddr, const void* g){
    asm volatile("cp.async.cg.shared.global [%0], [%1], 16;" :: "r"(saddr), "l"(g));
}
#define CP_COMMIT() asm volatile("cp.async.commit_group;" ::: "memory")
#define CP_WAIT(n)  asm volatile("cp.async.wait_group %0;" :: "n"(n) : "memory")

__device__ __forceinline__ void ldsm_x4(uint32_t* r, uint32_t a){
    asm volatile("ldmatrix.sync.aligned.m8n8.x4.shared.b16 {%0,%1,%2,%3}, [%4];"
        : "=r"(r[0]),"=r"(r[1]),"=r"(r[2]),"=r"(r[3]) : "r"(a));
}
__device__ __forceinline__ void mma16816(float* d, const uint32_t* a, const uint32_t* b){
    asm volatile("mma.sync.aligned.m16n8k16.row.col.f32.f16.f16.f32 "
        "{%0,%1,%2,%3},{%4,%5,%6,%7},{%8,%9},{%0,%1,%2,%3};"
        : "+f"(d[0]),"+f"(d[1]),"+f"(d[2]),"+f"(d[3])
        : "r"(a[0]),"r"(a[1]),"r"(a[2]),"r"(a[3]), "r"(b[0]),"r"(b[1]));
}
__device__ __forceinline__ void imma16832(int32_t* d, const uint32_t* a, const uint32_t* b){
    asm volatile("mma.sync.aligned.m16n8k32.row.col.s32.s8.s8.s32 "
        "{%0,%1,%2,%3},{%4,%5,%6,%7},{%8,%9},{%10,%11,%12,%13};"
        : "=r"(d[0]),"=r"(d[1]),"=r"(d[2]),"=r"(d[3])
        : "r"(a[0]),"r"(a[1]),"r"(a[2]),"r"(a[3]), "r"(b[0]),"r"(b[1]),
          "r"(0),"r"(0),"r"(0),"r"(0));
}

// swizzled byte offset of 16B chunk (r, c) in a [rows x 64B] fp16 tile
__device__ __forceinline__ uint32_t sw_off(int r, int c){
    return (uint32_t)(r*64 + ((c ^ ((r>>1)&3))*16));
}
// swizzled byte offset of 16B chunk (r, c∈{0,1}) in a [rows x 32B] int8 tile
__device__ __forceinline__ uint32_t off32(int r, int c){
    return (uint32_t)(r*32 + ((c ^ ((r>>2)&1))*16));
}
__device__ __forceinline__ float gelu_exact(float v){
    return 0.5f * v * (1.0f + erff(v * 0.70710678118654752440f));
}

// ---------------- elementwise kernels ----------------
__global__ void __launch_bounds__(128) quant_x_kernel(const float* __restrict__ x,
                                                      const int* __restrict__ ridx){
    int row = blockIdx.x;
    const float* xr = x + (size_t)row * QD;
    float v[9]; float mx = 0.f;
    int tid = threadIdx.x;
#pragma unroll
    for (int i = 0; i < 9; i++){
        int d = tid + i*128;
        v[i] = xr[ridx[d]];
        mx = fmaxf(mx, fabsf(v[i]));
    }
#pragma unroll
    for (int o = 16; o > 0; o >>= 1) mx = fmaxf(mx, __shfl_xor_sync(0xffffffffu, mx, o));
    __shared__ float wmax[4];
    if ((tid & 31) == 0) wmax[tid >> 5] = mx;
    __syncthreads();
    mx = fmaxf(fmaxf(wmax[0], wmax[1]), fmaxf(wmax[2], wmax[3]));
    float scale = fmaxf(mx * (1.0f/127.0f), 1e-8f);
    if (tid == 0) g_scale1[row] = scale;
    __half*  qr  = g_q1  + (size_t)row * QD;
    int8_t*  qr8 = g_q1b + (size_t)row * QD;
#pragma unroll
    for (int i = 0; i < 9; i++){
        int d = tid + i*128;
        float q = rintf(v[i] / scale);
        q = fminf(fmaxf(q, -128.f), 127.f);
        qr[d]  = __float2half_rn(q);
        qr8[d] = (int8_t)q;
    }
}

// per-output-row (h) W1 split: fp16 hi + per-row-scaled int8 residual
__global__ void __launch_bounds__(384) convert_w1_kernel(const float* __restrict__ W1){
    int row = blockIdx.x;
    int tid = threadIdx.x;
    const float* wr = W1 + (size_t)row * QD;
    float r[3]; __half hi[3];
    float mx = 0.f;
#pragma unroll
    for (int i = 0; i < 3; i++){
        int d = tid + i*384;
        float w = wr[d];
        hi[i] = __float2half_rn(w);
        r[i]  = w - __half2float(hi[i]);
        mx = fmaxf(mx, fabsf(r[i]));
    }
#pragma unroll
    for (int o = 16; o > 0; o >>= 1) mx = fmaxf(mx, __shfl_xor_sync(0xffffffffu, mx, o));
    __shared__ float wmax[12];
    if ((tid & 31) == 0) wmax[tid >> 5] = mx;
    __syncthreads();
    mx = 0.f;
#pragma unroll
    for (int i = 0; i < 12; i++) mx = fmaxf(mx, wmax[i]);
    float s = (mx > 0.f) ? (mx * (1.0f/127.0f)) : 1.0f;
    if (tid == 0) g_w1rs[row] = s;
#pragma unroll
    for (int i = 0; i < 3; i++){
        int d = tid + i*384;
        float q = rintf(r[i] / s);
        q = fminf(fmaxf(q, -127.f), 127.f);
        g_w1hi[(size_t)row*QD + d] = hi[i];
        g_w1r [(size_t)row*QD + d] = (int8_t)q;
    }
}

__global__ void __launch_bounds__(256) convert_w2_kernel(const float* __restrict__ W2){
    size_t i = (size_t)blockIdx.x * blockDim.x + threadIdx.x;
    if (i >= (size_t)QD * QH) return;
    g_w2h[i] = __float2half_rn(W2[i]);
}

__global__ void __launch_bounds__(256) quant_h_kernel(){
    int row = blockIdx.x;
    int tid = threadIdx.x;
    const float* hr = g_h + (size_t)row * QH;
    float v[18]; float mx = 0.f;
#pragma unroll
    for (int i = 0; i < 18; i++){
        v[i] = hr[tid + i*256];
        mx = fmaxf(mx, fabsf(v[i]));
    }
#pragma unroll
    for (int o = 16; o > 0; o >>= 1) mx = fmaxf(mx, __shfl_xor_sync(0xffffffffu, mx, o));
    __shared__ float wmax[8];
    if ((tid & 31) == 0) wmax[tid >> 5] = mx;
    __syncthreads();
    mx = 0.f;
#pragma unroll
    for (int i = 0; i < 8; i++) mx = fmaxf(mx, wmax[i]);
    float s = fmaxf(mx * (1.0f/127.0f), 1e-8f);
    if (tid == 0) g_scale2[row] = s;
    __half* qr = g_q2 + (size_t)row * QH;
#pragma unroll
    for (int i = 0; i < 18; i++){
        int d = tid + i*256;
        float q = rintf(v[i] / s);
        q = fminf(fmaxf(q, -128.f), 127.f);
        qr[d] = __float2half_rn(q);
    }
}

// ---------------- GEMM: CTA 256x128x32, 8 warps (4m x 2n), warp 64x64 ----
constexpr int BM = 256, BN = 128, BK = 32;
constexpr int ATILE  = BM * 64;   // 16 KB fp16 A
constexpr int A8TILE = BM * 32;   // 8 KB int8 A
constexpr int BTILE  = BN * 64;   // 8 KB fp16 B
constexpr int BRTILE = BN * 32;   // 4 KB int8 B residual
constexpr int STAGES = 4;
constexpr int GM = 16;

// FC1: acc = q1*W1hi (HMMA) + sum s_r[col]*(q1b*W1r) (IMMA); epi gelu(acc*s1+b1)->g_h
// FC2: acc = q2*W2h (HMMA); epi acc*s2+b2 -> out
template<bool FC1>
__global__ void __launch_bounds__(256, 1)
gemm_kernel(const float* __restrict__ bias, float* __restrict__ outArg){
    const __half*  __restrict__ Ah  = FC1 ? g_q1   : g_q2;
    const __half*  __restrict__ Bh  = FC1 ? g_w1hi : g_w2h;
    const int8_t*  __restrict__ A8  = g_q1b;
    const int8_t*  __restrict__ Br  = g_w1r;
    const float*   __restrict__ rsc = FC1 ? g_scale1 : g_scale2;
    float* __restrict__ outF        = FC1 ? (float*)g_h : outArg;
    const int K = FC1 ? QD : QH;
    const int N = FC1 ? QH : QD;
    const int nB = N / BN;
    const int NK = K / BK;

    int bid = blockIdx.x;
    int per = GM * nB;
    int grp = bid / per, rem = bid % per;
    int m0 = (grp * GM + (rem % GM)) * BM;
    int n0 = (rem / GM) * BN;

    extern __shared__ __align__(128) char smem[];
    uint32_t sAb  = smem_u32(smem);
    uint32_t sBhb = sAb  + STAGES*ATILE;
    uint32_t sA8b = sBhb + STAGES*BTILE;                 // FC1 only
    uint32_t sBrb = sA8b + STAGES*A8TILE;                // FC1 only

    int tid = threadIdx.x;
    int lane = tid & 31, wid = tid >> 5;
    int wm = wid >> 1, wn = wid & 1;

    float acc[4][8][4];
#pragma unroll
    for (int mt=0; mt<4; mt++)
#pragma unroll
        for (int nt=0; nt<8; nt++)
#pragma unroll
            for (int j=0; j<4; j++) acc[mt][nt][j] = 0.f;

    // per-column residual scales (FC1)
    float rs0[8], rs1[8];
    if (FC1){
#pragma unroll
        for (int nt = 0; nt < 8; nt++){
            int col = n0 + wn*64 + nt*8 + (lane & 3)*2;
            rs0[nt] = __ldg(g_w1rs + col);
            rs1[nt] = __ldg(g_w1rs + col + 1);
        }
    }

    auto load_stage = [&](int kt, int st){
        size_t k0 = (size_t)kt * BK;
        uint32_t sA = sAb + st*ATILE;
        uint32_t sB = sBhb + st*BTILE;
#pragma unroll
        for (int i = 0; i < 4; i++){
            int ch = tid + i*256;
            int r = ch >> 2, c = ch & 3;
            cp16(sA + sw_off(r,c), Ah + (size_t)(m0 + r)*K + k0 + c*8);
        }
#pragma unroll
        for (int i = 0; i < 2; i++){
            int ch = tid + i*256;
            int r = ch >> 2, c = ch & 3;
            cp16(sB + sw_off(r,c), Bh + (size_t)(n0 + r)*K + k0 + c*8);
        }
        if (FC1){
            uint32_t s8 = sA8b + st*A8TILE;
            uint32_t sR = sBrb + st*BRTILE;
#pragma unroll
            for (int i = 0; i < 2; i++){
                int ch = tid + i*256;
                int r = ch >> 1, c = ch & 1;
                cp16(s8 + off32(r,c), A8 + (size_t)(m0 + r)*K + k0 + c*16);
            }
            {
                int r = tid >> 1, c = tid & 1;
                cp16(sR + off32(r,c), Br + (size_t)(n0 + r)*K + k0 + c*16);
            }
        }
    };

    auto compute = [&](int st){
        uint32_t sA = sAb + st*ATILE;
        uint32_t sB = sBhb + st*BTILE;
        if (FC1){
            // ---- int8 residual (IMMA, k=32 in one shot) ----
            uint32_t s8 = sA8b + st*A8TILE;
            uint32_t sR = sBrb + st*BRTILE;
            uint32_t a8[4][4], b8[4][4];
            int rA = (lane & 7) + ((lane >> 3) & 1)*8;
            int hA = (lane >> 4) & 1;
#pragma unroll
            for (int mt = 0; mt < 4; mt++)
                ldsm_x4(a8[mt], s8 + off32(wm*64 + mt*16 + rA, hA));
            int rB = (lane & 7) + ((lane >> 4) & 1)*8;
            int hB = (lane >> 3) & 1;
#pragma unroll
            for (int p = 0; p < 4; p++)
                ldsm_x4(b8[p], sR + off32(wn*64 + p*16 + rB, hB));
#pragma unroll
            for (int mt = 0; mt < 4; mt++)
#pragma unroll
                for (int p = 0; p < 4; p++){
                    int32_t d0[4], d1[4];
                    imma16832(d0, a8[mt], &b8[p][0]);
                    imma16832(d1, a8[mt], &b8[p][2]);
                    int u = 2*p, v = 2*p + 1;
                    acc[mt][u][0] += (float)d0[0] * rs0[u];
                    acc[mt][u][1] += (float)d0[1] * rs1[u];
                    acc[mt][u][2] += (float)d0[2] * rs0[u];
                    acc[mt][u][3] += (float)d0[3] * rs1[u];
                    acc[mt][v][0] += (float)d1[0] * rs0[v];
                    acc[mt][v][1] += (float)d1[1] * rs1[v];
                    acc[mt][v][2] += (float)d1[2] * rs0[v];
                    acc[mt][v][3] += (float)d1[3] * rs1[v];
                }
        }
        // ---- fp16 hi (HMMA), two k16 halves ----
#pragma unroll
        for (int kt = 0; kt < 2; kt++){
            uint32_t a[4][4];
#pragma unroll
            for (int mt = 0; mt < 4; mt++){
                int r = wm*64 + mt*16 + (lane & 15);
                int c = kt*2 + (lane >> 4);
                ldsm_x4(a[mt], sA + sw_off(r, c));
            }
            int rb = wn*64 + ((lane >> 4) << 3) + (lane & 7);
            int cb = kt*2 + ((lane >> 3) & 1);
            uint32_t b[4][4];
#pragma unroll
            for (int p = 0; p < 4; p++)
                ldsm_x4(b[p], sB + sw_off(rb + p*16, cb));
#pragma unroll
            for (int mt = 0; mt < 4; mt++)
#pragma unroll
                for (int p = 0; p < 4; p++){
                    mma16816(acc[mt][p*2+0], a[mt], &b[p][0]);
                    mma16816(acc[mt][p*2+1], a[mt], &b[p][2]);
                }
        }
    };

    // prologue: STAGES-1 stages in flight
#pragma unroll
    for (int s = 0; s < STAGES-1; s++){
        load_stage(s, s);
        CP_COMMIT();
    }
    for (int kt = 0; kt < NK; kt++){
        CP_WAIT(STAGES-2);
        __syncthreads();
        compute(kt % STAGES);
        if (kt + STAGES-1 < NK)
            load_stage(kt + STAGES-1, (kt + STAGES-1) % STAGES);
        CP_COMMIT();
    }

    // ---- epilogue ----
#pragma unroll
    for (int mt = 0; mt < 4; mt++){
#pragma unroll
        for (int hf = 0; hf < 2; hf++){
            int row = m0 + wm*64 + mt*16 + (lane >> 2) + 8*hf;
            float s = __ldg(rsc + row);
#pragma unroll
            for (int nt = 0; nt < 8; nt++){
                int col = n0 + wn*64 + nt*8 + (lane & 3)*2;
                float v0 = acc[mt][nt][hf*2 + 0] * s + __ldg(bias + col);
                float v1 = acc[mt][nt][hf*2 + 1] * s + __ldg(bias + col + 1);
                if (FC1){
                    v0 = gelu_exact(v0);
                    v1 = gelu_exact(v1);
                }
                *(float2*)(outF + (size_t)row * N + col) = make_float2(v0, v1);
            }
        }
    }
}

// ---------------- launch ----------------
extern "C" void kernel_launch(void* const* d_in, const int* in_sizes, int n_in,
                              void* d_out, int out_size){
    (void)in_sizes; (void)n_in; (void)out_size;
    const float* x    = (const float*)d_in[0];
    const int*   ridx = (const int*)  d_in[1];
    const float* W1   = (const float*)d_in[2];
    const float* b1   = (const float*)d_in[3];
    const float* W2   = (const float*)d_in[4];
    const float* b2   = (const float*)d_in[5];
    float* out = (float*)d_out;

    const int SMEM1 = STAGES * (ATILE + BTILE + A8TILE + BRTILE);  // 147456
    const int SMEM2 = STAGES * (ATILE + BTILE);                    // 98304
    cudaFuncSetAttribute(gemm_kernel<true>,  cudaFuncAttributeMaxDynamicSharedMemorySize, SMEM1);
    cudaFuncSetAttribute(gemm_kernel<false>, cudaFuncAttributeMaxDynamicSharedMemorySize, SMEM2);

    quant_x_kernel<<<QM, 128>>>(x, ridx);
    convert_w1_kernel<<<QH, 384>>>(W1);
    {
        size_t Nw = (size_t)QD * QH;
        convert_w2_kernel<<<(unsigned)((Nw + 255) / 256), 256>>>(W2);
    }
    gemm_kernel<true> <<<(QH/BN) * (QM/BM), 256, SMEM1>>>(b1, nullptr);
    quant_h_kernel<<<QM, 256>>>();
    gemm_kernel<false><<<(QD/BN) * (QM/BM), 256, SMEM2>>>(b2, out);
}